// round 12
// baseline (speedup 1.0000x reference)
#include <cuda_runtime.h>
#include <cuda_bf16.h>
#include <math.h>

// FactorizedPrior: z_hat = round(z); likelihoods = clip(cdf(z_hat+0.5)-cdf(z_hat-0.5), 1e-9)
// cdf = sigmoid( 4-layer per-channel tiny MLP with softplus'd weights ).
// With factors f==0, the MLP collapses per channel to logit = a[c]*x + d[c].
// R12 = recombination of measured-best pieces:
//   setup: 192 blocks x 32 threads (one channel/block, one softplus/thread)
//          -> g_ad[c] = {a, d, K=e^a, per-channel flag}; ~1.5us wall.
//   main:  R3's proven one-shot geometry (24576 x 256, ILP=1, plain ld/st),
//          with single-divide likelihood: E=e^{-(a(x+.5)+d)},
//          up-lo = E(K-1)/((1+E)(1+EK)).

#define NCH 192
#define NB 32
#define NHW 4096                 // 64*64
#define NELEM (NB * NCH * NHW)   // 25165824
#define N4 (NELEM / 4)           // 6291456 float4s
#define GRID_MAIN (N4 / 256)     // 24576 blocks, one float4 per thread

__device__ float4 g_ad[NCH];     // {a, d, K=e^a, flag}

__device__ __forceinline__ float softplus_fast(float x) {
    // log(1+e^x) = max(x,0) + log(1+e^-|x|), fast-math MUFU version.
    float e = __expf(-fabsf(x));
    return fmaxf(x, 0.f) + __logf(1.f + e);
}

__global__ void setup_kernel(const float* __restrict__ m0, const float* __restrict__ m1,
                             const float* __restrict__ m2, const float* __restrict__ m3,
                             const float* __restrict__ b0, const float* __restrict__ b1,
                             const float* __restrict__ b2, const float* __restrict__ b3,
                             const float* __restrict__ f0, const float* __restrict__ f1,
                             const float* __restrict__ f2) {
    __shared__ float sw[24];     // softplus'd weights: w0[3] W1[9] W2[9] w3[3]
    int c = blockIdx.x;
    int t = threadIdx.x;

    if (t < 24) {
        float raw;
        if (t < 3)       raw = m0[c * 3 + t];
        else if (t < 12) raw = m1[c * 9 + (t - 3)];
        else if (t < 21) raw = m2[c * 9 + (t - 12)];
        else             raw = m3[c * 3 + (t - 21)];
        sw[t] = softplus_fast(raw);
    }

    int nz = 0;
    if (t < 9) {
        float fv = (t < 3) ? f0[c * 3 + t] : (t < 6) ? f1[c * 3 + (t - 3)] : f2[c * 3 + (t - 6)];
        nz = (fv != 0.f);
    }
    nz = __any_sync(0xffffffffu, nz);   // blockDim == 32
    __syncthreads();                    // publish sw

    if (t == 0) {
        const float* w0 = sw;
        const float* W1 = sw + 3;
        const float* W2 = sw + 12;
        const float* w3 = sw + 21;

        float va[3], vd[3], ta[3], td[3];
        #pragma unroll
        for (int i = 0; i < 3; i++) { va[i] = w0[i]; vd[i] = b0[c * 3 + i]; }
        #pragma unroll
        for (int r = 0; r < 3; r++) {
            ta[r] = W1[r*3+0]*va[0] + W1[r*3+1]*va[1] + W1[r*3+2]*va[2];
            td[r] = W1[r*3+0]*vd[0] + W1[r*3+1]*vd[1] + W1[r*3+2]*vd[2] + b1[c*3+r];
        }
        #pragma unroll
        for (int r = 0; r < 3; r++) {
            va[r] = W2[r*3+0]*ta[0] + W2[r*3+1]*ta[1] + W2[r*3+2]*ta[2];
            vd[r] = W2[r*3+0]*td[0] + W2[r*3+1]*td[1] + W2[r*3+2]*td[2] + b2[c*3+r];
        }
        float a = w3[0]*va[0] + w3[1]*va[1] + w3[2]*va[2];
        float d = w3[0]*vd[0] + w3[1]*vd[1] + w3[2]*vd[2] + b3[c];

        g_ad[c] = make_float4(a, d, __expf(a), nz ? 1.f : 0.f);
    }
}

// ---------------- general (f != 0) fallback: precise, per-element, dead with
// the dataset inputs; isolated from the fast path's register allocation. -----
__device__ __noinline__ float cdf_raw(int c, float x,
                                      const float* m0, const float* m1,
                                      const float* m2, const float* m3,
                                      const float* b0, const float* b1,
                                      const float* b2, const float* b3,
                                      const float* f0, const float* f1,
                                      const float* f2) {
    float v[3], u[3];
    #pragma unroll
    for (int r = 0; r < 3; r++) {
        float w = (m0[c*3+r] > 0.f) ? m0[c*3+r] + log1pf(expf(-m0[c*3+r])) : log1pf(expf(m0[c*3+r]));
        v[r] = fmaf(w, x, b0[c*3+r]);
        v[r] = fmaf(tanhf(f0[c*3+r]), tanhf(v[r]), v[r]);
    }
    #pragma unroll
    for (int r = 0; r < 3; r++) {
        u[r] = b1[c*3+r];
        #pragma unroll
        for (int k = 0; k < 3; k++) {
            float m = m1[c*9 + r*3 + k];
            float w = (m > 0.f) ? m + log1pf(expf(-m)) : log1pf(expf(m));
            u[r] = fmaf(w, v[k], u[r]);
        }
        u[r] = fmaf(tanhf(f1[c*3+r]), tanhf(u[r]), u[r]);
    }
    #pragma unroll
    for (int r = 0; r < 3; r++) {
        v[r] = b2[c*3+r];
        #pragma unroll
        for (int k = 0; k < 3; k++) {
            float m = m2[c*9 + r*3 + k];
            float w = (m > 0.f) ? m + log1pf(expf(-m)) : log1pf(expf(m));
            v[r] = fmaf(w, u[k], v[r]);
        }
        v[r] = fmaf(tanhf(f2[c*3+r]), tanhf(v[r]), v[r]);
    }
    float l = b3[c];
    #pragma unroll
    for (int k = 0; k < 3; k++) {
        float m = m3[c*3+k];
        float w = (m > 0.f) ? m + log1pf(expf(-m)) : log1pf(expf(m));
        l = fmaf(w, v[k], l);
    }
    return 1.f / (1.f + expf(-l));
}

__global__ void __launch_bounds__(256) fp_main_kernel(
        const float4* __restrict__ z, float* __restrict__ out,
        const float* __restrict__ m0, const float* __restrict__ m1,
        const float* __restrict__ m2, const float* __restrict__ m3,
        const float* __restrict__ b0, const float* __restrict__ b1,
        const float* __restrict__ b2, const float* __restrict__ b3,
        const float* __restrict__ f0, const float* __restrict__ f1,
        const float* __restrict__ f2) {
    int i = blockIdx.x * 256 + threadIdx.x;   // grid sized exactly: i < N4
    int c = (i >> 10) % NCH;                  // 1024 float4 per (b,c) plane

    float4 zv = z[i];
    float4 p  = g_ad[c];                      // {a, d, K, flag}; warp-uniform c
    float4 zh, lk;

    if (p.w == 0.f) {                         // warp-uniform branch
        #pragma unroll
        for (int j = 0; j < 4; j++) {
            float x  = rintf((&zv.x)[j]);     // round half-to-even == jnp.round
            float t  = fmaf(p.x, x + 0.5f, p.y);   // a*(x+0.5)+d : upper logit
            float E  = __expf(-t);
            // up - lo = E*(K-1) / ((1+E)*(1+E*K)) : one divide, no cancellation
            float num = E * (p.z - 1.f);
            float den = (1.f + E) * fmaf(E, p.z, 1.f);
            (&zh.x)[j] = x;
            (&lk.x)[j] = fmaxf(__fdividef(num, den), 1e-9f);
        }
    } else {
        #pragma unroll
        for (int j = 0; j < 4; j++) {
            float x = rintf((&zv.x)[j]);
            (&zh.x)[j] = x;
            (&lk.x)[j] = fmaxf(cdf_raw(c, x + 0.5f, m0,m1,m2,m3,b0,b1,b2,b3,f0,f1,f2)
                             - cdf_raw(c, x - 0.5f, m0,m1,m2,m3,b0,b1,b2,b3,f0,f1,f2), 1e-9f);
        }
    }

    reinterpret_cast<float4*>(out)[i] = zh;            // z_hat  [0, N)
    reinterpret_cast<float4*>(out + NELEM)[i] = lk;    // likes  [N, 2N)
}

extern "C" void kernel_launch(void* const* d_in, const int* in_sizes, int n_in,
                              void* d_out, int out_size) {
    const float* z  = (const float*)d_in[0];
    const float* m0 = (const float*)d_in[1];
    const float* m1 = (const float*)d_in[2];
    const float* m2 = (const float*)d_in[3];
    const float* m3 = (const float*)d_in[4];
    const float* b0 = (const float*)d_in[5];
    const float* b1 = (const float*)d_in[6];
    const float* b2 = (const float*)d_in[7];
    const float* b3 = (const float*)d_in[8];
    const float* f0 = (const float*)d_in[9];
    const float* f1 = (const float*)d_in[10];
    const float* f2 = (const float*)d_in[11];

    setup_kernel<<<NCH, 32>>>(m0, m1, m2, m3, b0, b1, b2, b3, f0, f1, f2);
    fp_main_kernel<<<GRID_MAIN, 256>>>((const float4*)z, (float*)d_out,
                                       m0, m1, m2, m3, b0, b1, b2, b3, f0, f1, f2);
}